// round 2
// baseline (speedup 1.0000x reference)
#include <cuda_runtime.h>
#include <math.h>

#define HID   2048
#define NB    2
#define SQ    2048
#define NHEAD 16
#define HD    128
#define MROWS (NB * SQ)        /* 4096 */
#define NW    (HID * HID)      /* 4194304 */

/* ---------------- scratch (device globals; no allocation allowed) -------- */
__device__ float g_W[4][NW];            /* q,k,v,o weights, row-major [out][in] */
__device__ float g_Q[MROWS * HID];
__device__ float g_K[MROWS * HID];
__device__ float g_V[MROWS * HID];
__device__ float g_A[MROWS * HID];      /* attention output before O-proj */

/* ---------------- weight reconstruction (fp32-matched jnp.interp) -------- */
/* ncp comes from in_sizes at runtime — N_CP = int(2048*2048/128.9) = 32539, */
/* NOT the 32540 the reference comment claims.                               */
__global__ void build_weights(const float* __restrict__ cpq,
                              const float* __restrict__ cpk,
                              const float* __restrict__ cpv,
                              const float* __restrict__ cpo,
                              int ncp) {
    int i = blockIdx.x * 256 + threadIdx.x;
    if (i >= NW) return;
    const float dT = 1.0f / (float)(NW - 1);
    const float dX = 1.0f / (float)(ncp - 1);
    float t = (float)i * dT;                      /* fp32, matching linspace */
    int j = (int)((double)t * (double)(ncp - 1)); /* initial guess */
    if (j > ncp - 2) j = ncp - 2;
    if (j < 0) j = 0;
    /* fix up against the fp32 knot grid (matches searchsorted on fp32 xp) */
    while (j < ncp - 2 && (float)(j + 1) * dX <= t) j++;
    while (j > 0 && (float)j * dX > t) j--;
    float x0 = (float)j * dX;
    float x1 = (float)(j + 1) * dX;
    float f  = (t - x0) / (x1 - x0);
    float aq = cpq[j], ak = cpk[j], av = cpv[j], ao = cpo[j];
    g_W[0][i] = fmaf(cpq[j + 1] - aq, f, aq);
    g_W[1][i] = fmaf(cpk[j + 1] - ak, f, ak);
    g_W[2][i] = fmaf(cpv[j + 1] - av, f, av);
    g_W[3][i] = fmaf(cpo[j + 1] - ao, f, ao);
}

/* ---------------- fp32 NT SGEMM: C[M,N] = A[M,K] * B[N,K]^T -------------- */
/* 128x128 tile, BK=8, 256 threads, 8x8 per thread. Grid: (N/128, M/128).   */
__global__ void __launch_bounds__(256) sgemm_nt(const float* __restrict__ A,
                                                const float* __restrict__ B,
                                                float* __restrict__ C,
                                                int N, int K) {
    __shared__ float As[8][128];
    __shared__ float Bs[8][128];
    int tid = threadIdx.x;
    int m0 = blockIdx.y * 128;
    int n0 = blockIdx.x * 128;
    int lr = tid >> 1;            /* 0..127 */
    int lc = (tid & 1) * 4;       /* 0 or 4 */
    int tx = tid & 15;
    int ty = tid >> 4;

    const float* Aptr = A + (m0 + lr) * K + lc;
    const float* Bptr = B + (n0 + lr) * K + lc;

    float acc[8][8];
#pragma unroll
    for (int i = 0; i < 8; i++)
#pragma unroll
        for (int jj = 0; jj < 8; jj++) acc[i][jj] = 0.0f;

    for (int k0 = 0; k0 < K; k0 += 8) {
        float4 avv = *(const float4*)(Aptr + k0);
        float4 bvv = *(const float4*)(Bptr + k0);
        __syncthreads();
        As[lc + 0][lr] = avv.x; As[lc + 1][lr] = avv.y;
        As[lc + 2][lr] = avv.z; As[lc + 3][lr] = avv.w;
        Bs[lc + 0][lr] = bvv.x; Bs[lc + 1][lr] = bvv.y;
        Bs[lc + 2][lr] = bvv.z; Bs[lc + 3][lr] = bvv.w;
        __syncthreads();
#pragma unroll
        for (int kk = 0; kk < 8; kk++) {
            float a[8], b[8];
#pragma unroll
            for (int i = 0; i < 8; i++) a[i] = As[kk][ty * 8 + i];
#pragma unroll
            for (int jj = 0; jj < 8; jj++) b[jj] = Bs[kk][tx * 8 + jj];
#pragma unroll
            for (int i = 0; i < 8; i++)
#pragma unroll
                for (int jj = 0; jj < 8; jj++)
                    acc[i][jj] = fmaf(a[i], b[jj], acc[i][jj]);
        }
    }
#pragma unroll
    for (int i = 0; i < 8; i++) {
        float* Crow = C + (m0 + ty * 8 + i) * N + n0 + tx * 8;
#pragma unroll
        for (int jj = 0; jj < 8; jj++) Crow[jj] = acc[i][jj];
    }
}

/* ---------------- causal flash attention (fp32, online softmax) ---------- */
#define BM 64
#define BN 64
#define TSTRIDE 132            /* 128 + 4 pad (keeps 16B align, breaks conflicts) */
#define PSTRIDE 68             /* 64 + 4 pad */

extern __shared__ float sh[];

__global__ void __launch_bounds__(256) flash_attn(const float* __restrict__ Q,
                                                  const float* __restrict__ Km,
                                                  const float* __restrict__ Vm,
                                                  float* __restrict__ O) {
    float* Qs = sh;
    float* Ks = Qs + BM * TSTRIDE;
    float* Vs = Ks + BN * TSTRIDE;
    float* Ps = Vs + BN * TSTRIDE;

    int qb = blockIdx.x, h = blockIdx.y, b = blockIdx.z;
    int tid = threadIdx.x, tx = tid & 15, ty = tid >> 4;
    int q0 = qb * BM;
    const float scale = 0.08838834764831845f;  /* 1/sqrt(128) */

    const float* Qbase = Q + (b * SQ) * HID + h * HD;
    for (int it = tid; it < BM * (HD / 4); it += 256) {
        int r = it >> 5, c4 = (it & 31) << 2;
        *(float4*)(Qs + r * TSTRIDE + c4) =
            *(const float4*)(Qbase + (q0 + r) * HID + c4);
    }

    float m_i[4], l_i[4], o[4][8];
#pragma unroll
    for (int i = 0; i < 4; i++) {
        m_i[i] = -1e30f; l_i[i] = 0.0f;
#pragma unroll
        for (int jj = 0; jj < 8; jj++) o[i][jj] = 0.0f;
    }

    for (int kb = 0; kb <= qb; kb++) {
        int k0 = kb * BN;
        const float* Kbase = Km + (b * SQ + k0) * HID + h * HD;
        const float* Vbase = Vm + (b * SQ + k0) * HID + h * HD;
        __syncthreads();
        for (int it = tid; it < BN * (HD / 4); it += 256) {
            int r = it >> 5, c4 = (it & 31) << 2;
            *(float4*)(Ks + r * TSTRIDE + c4) = *(const float4*)(Kbase + r * HID + c4);
            *(float4*)(Vs + r * TSTRIDE + c4) = *(const float4*)(Vbase + r * HID + c4);
        }
        __syncthreads();

        /* S = Q K^T : rows ty*4+i, cols tx+16*j */
        float s[4][4];
#pragma unroll
        for (int i = 0; i < 4; i++)
#pragma unroll
            for (int jj = 0; jj < 4; jj++) s[i][jj] = 0.0f;

#pragma unroll 4
        for (int d = 0; d < HD; d++) {
            float qr[4], kv[4];
#pragma unroll
            for (int i = 0; i < 4; i++) qr[i] = Qs[(ty * 4 + i) * TSTRIDE + d];
#pragma unroll
            for (int jj = 0; jj < 4; jj++) kv[jj] = Ks[(tx + 16 * jj) * TSTRIDE + d];
#pragma unroll
            for (int i = 0; i < 4; i++)
#pragma unroll
                for (int jj = 0; jj < 4; jj++)
                    s[i][jj] = fmaf(qr[i], kv[jj], s[i][jj]);
        }

        /* scale + causal mask */
#pragma unroll
        for (int i = 0; i < 4; i++) {
            int qi = q0 + ty * 4 + i;
#pragma unroll
            for (int jj = 0; jj < 4; jj++) {
                int ki = k0 + tx + 16 * jj;
                s[i][jj] = s[i][jj] * scale + (ki > qi ? -1e9f : 0.0f);
            }
        }

        /* online softmax per row (row group = 16 consecutive lanes) */
#pragma unroll
        for (int i = 0; i < 4; i++) {
            float mt = fmaxf(fmaxf(s[i][0], s[i][1]), fmaxf(s[i][2], s[i][3]));
#pragma unroll
            for (int off = 1; off < 16; off <<= 1)
                mt = fmaxf(mt, __shfl_xor_sync(0xffffffffu, mt, off));
            float mnew = fmaxf(m_i[i], mt);
            float alpha = __expf(m_i[i] - mnew);
            m_i[i] = mnew;
            float rowsum = 0.0f;
#pragma unroll
            for (int jj = 0; jj < 4; jj++) {
                float p = __expf(s[i][jj] - mnew);
                Ps[(ty * 4 + i) * PSTRIDE + tx + 16 * jj] = p;
                rowsum += p;
            }
#pragma unroll
            for (int off = 1; off < 16; off <<= 1)
                rowsum += __shfl_xor_sync(0xffffffffu, rowsum, off);
            l_i[i] = l_i[i] * alpha + rowsum;
#pragma unroll
            for (int jj = 0; jj < 8; jj++) o[i][jj] *= alpha;
        }
        __syncwarp();   /* Ps producers/consumers share the warp */

        /* O += P V : d-cols tx+16*j */
#pragma unroll 2
        for (int kk = 0; kk < BN; kk++) {
            float pv[4], vv[8];
#pragma unroll
            for (int i = 0; i < 4; i++) pv[i] = Ps[(ty * 4 + i) * PSTRIDE + kk];
#pragma unroll
            for (int jj = 0; jj < 8; jj++) vv[jj] = Vs[kk * TSTRIDE + tx + 16 * jj];
#pragma unroll
            for (int i = 0; i < 4; i++)
#pragma unroll
                for (int jj = 0; jj < 8; jj++)
                    o[i][jj] = fmaf(pv[i], vv[jj], o[i][jj]);
        }
    }

#pragma unroll
    for (int i = 0; i < 4; i++) {
        float inv = 1.0f / l_i[i];
        float* Orow = O + (b * SQ + q0 + ty * 4 + i) * HID + h * HD + tx;
#pragma unroll
        for (int jj = 0; jj < 8; jj++) Orow[16 * jj] = o[i][jj] * inv;
    }
}

/* ---------------- launcher ---------------------------------------------- */
extern "C" void kernel_launch(void* const* d_in, const int* in_sizes, int n_in,
                              void* d_out, int out_size) {
    (void)n_in; (void)out_size;
    const float* x   = (const float*)d_in[0];
    const float* cpq = (const float*)d_in[1];
    const float* cpk = (const float*)d_in[2];
    const float* cpv = (const float*)d_in[3];
    const float* cpo = (const float*)d_in[4];
    float* out = (float*)d_out;
    int ncp = in_sizes[1];   /* actual control-point count from the harness */

    float *pW, *pQ, *pK, *pV, *pA;
    cudaGetSymbolAddress((void**)&pW, g_W);
    cudaGetSymbolAddress((void**)&pQ, g_Q);
    cudaGetSymbolAddress((void**)&pK, g_K);
    cudaGetSymbolAddress((void**)&pV, g_V);
    cudaGetSymbolAddress((void**)&pA, g_A);

    build_weights<<<(NW + 255) / 256, 256>>>(cpq, cpk, cpv, cpo, ncp);

    dim3 gg(HID / 128, MROWS / 128);
    sgemm_nt<<<gg, 256>>>(x, pW + 0 * (size_t)NW, pQ, HID, HID);
    sgemm_nt<<<gg, 256>>>(x, pW + 1 * (size_t)NW, pK, HID, HID);
    sgemm_nt<<<gg, 256>>>(x, pW + 2 * (size_t)NW, pV, HID, HID);

    size_t shb = (size_t)(3 * BM * TSTRIDE + BM * PSTRIDE) * sizeof(float);
    cudaFuncSetAttribute(flash_attn, cudaFuncAttributeMaxDynamicSharedMemorySize,
                         (int)shb);
    flash_attn<<<dim3(SQ / BM, NHEAD, NB), 256, shb>>>(pQ, pK, pV, pA);

    sgemm_nt<<<gg, 256>>>(pA, pW + 3 * (size_t)NW, out, HID, HID);
}

// round 4
// speedup vs baseline: 1.9159x; 1.9159x over previous
#include <cuda_runtime.h>
#include <cuda_bf16.h>
#include <math.h>
#include <stdint.h>

#define HID   2048
#define NB    2
#define SQ    2048
#define NHEAD 16
#define HD    128
#define MROWS (NB * SQ)        /* 4096 */
#define NW    (HID * HID)      /* 4194304 */
#define KDIM  2048

/* ---------------- scratch (device globals; no allocation allowed) -------- */
__device__ float g_W[4][NW];            /* q,k,v,o weights, row-major [out][in] */
__device__ float g_Q[MROWS * HID];
__device__ float g_K[MROWS * HID];
__device__ float g_V[MROWS * HID];
__device__ float g_A[MROWS * HID];      /* attention output before O-proj */

__device__ __forceinline__ uint32_t smem_u32(const void* p) {
    uint32_t a;
    asm("{ .reg .u64 t; cvta.to.shared.u64 t, %1; cvt.u32.u64 %0, t; }"
        : "=r"(a) : "l"(p));
    return a;
}

/* ---------------- weight reconstruction (fp32-matched jnp.interp) -------- */
__global__ void build_weights(const float* __restrict__ cpq,
                              const float* __restrict__ cpk,
                              const float* __restrict__ cpv,
                              const float* __restrict__ cpo,
                              int ncp) {
    int i = blockIdx.x * 256 + threadIdx.x;
    if (i >= NW) return;
    const float dT = 1.0f / (float)(NW - 1);
    const float dX = 1.0f / (float)(ncp - 1);
    float t = (float)i * dT;                      /* fp32, matching linspace */
    int j = (int)((double)t * (double)(ncp - 1));
    if (j > ncp - 2) j = ncp - 2;
    if (j < 0) j = 0;
    while (j < ncp - 2 && (float)(j + 1) * dX <= t) j++;
    while (j > 0 && (float)j * dX > t) j--;
    float x0 = (float)j * dX;
    float x1 = (float)(j + 1) * dX;
    float f  = (t - x0) / (x1 - x0);
    float aq = cpq[j], ak = cpk[j], av = cpv[j], ao = cpo[j];
    g_W[0][i] = fmaf(cpq[j + 1] - aq, f, aq);
    g_W[1][i] = fmaf(cpk[j + 1] - ak, f, ak);
    g_W[2][i] = fmaf(cpv[j + 1] - av, f, av);
    g_W[3][i] = fmaf(cpo[j + 1] - ao, f, ao);
}

/* =============== bf16x3 split HMMA GEMM: C[M,2048] = A * B^T ============= */
/* A[M,2048], B[2048,2048] fp32 row-major. CTA 128x128, 512 thr, warp 32x32. */
#define KC     32
#define NCHUNK (KDIM / KC)
#define SA     40                       /* halfwords per smem row (80 B)    */
#define TILE_HW (128 * SA)              /* halfwords per tile               */
#define TILE_B  (TILE_HW * 2)           /* 10240 bytes                      */
#define BUF_B   (4 * TILE_B)            /* Ah, Al, Bh, Bl                   */
#define GEMM_SMEM (2 * BUF_B)           /* 81920 bytes                      */

__device__ __forceinline__ void ldm_x4(uint32_t* r, uint32_t addr) {
    asm volatile("ldmatrix.sync.aligned.m8n8.x4.shared.b16 {%0,%1,%2,%3}, [%4];"
                 : "=r"(r[0]), "=r"(r[1]), "=r"(r[2]), "=r"(r[3]) : "r"(addr));
}
__device__ __forceinline__ void mma_bf16(float* d, const uint32_t* a,
                                         uint32_t b0, uint32_t b1) {
    asm volatile("mma.sync.aligned.m16n8k16.row.col.f32.bf16.bf16.f32 "
                 "{%0,%1,%2,%3},{%4,%5,%6,%7},{%8,%9},{%0,%1,%2,%3};"
                 : "+f"(d[0]), "+f"(d[1]), "+f"(d[2]), "+f"(d[3])
                 : "r"(a[0]), "r"(a[1]), "r"(a[2]), "r"(a[3]), "r"(b0), "r"(b1));
}
__device__ __forceinline__ void split4(float4 v, uint2& hi, uint2& lo) {
    __nv_bfloat162 h0 = __float22bfloat162_rn(make_float2(v.x, v.y));
    __nv_bfloat162 h1 = __float22bfloat162_rn(make_float2(v.z, v.w));
    float2 f0 = __bfloat1622float2(h0), f1 = __bfloat1622float2(h1);
    __nv_bfloat162 l0 = __float22bfloat162_rn(make_float2(v.x - f0.x, v.y - f0.y));
    __nv_bfloat162 l1 = __float22bfloat162_rn(make_float2(v.z - f1.x, v.w - f1.y));
    hi = make_uint2(*(uint32_t*)&h0, *(uint32_t*)&h1);
    lo = make_uint2(*(uint32_t*)&l0, *(uint32_t*)&l1);
}

__global__ void __launch_bounds__(512) gemm_hmma(const float* __restrict__ A,
                                                 const float* __restrict__ B,
                                                 float* __restrict__ C) {
    extern __shared__ char shg[];
    __nv_bfloat16* s = (__nv_bfloat16*)shg;
    const uint32_t sb = smem_u32(shg);
    const int tid = threadIdx.x;
    const int lane = tid & 31, wid = tid >> 5;
    const int warp_m = wid >> 2, warp_n = wid & 3;     /* 4 x 4 warps */
    const int m0 = blockIdx.y * 128, n0 = blockIdx.x * 128;

    /* gmem load coords: 2 float4 each from A and B per chunk */
    const int rL = tid >> 3, cL = (tid & 7) << 2;
    const float* Ap = A + (size_t)(m0 + rL) * KDIM + cL;
    const float* Bp = B + (size_t)(n0 + rL) * KDIM + cL;

    float acc[2][4][4];
#pragma unroll
    for (int i = 0; i < 2; i++)
#pragma unroll
        for (int j = 0; j < 4; j++)
#pragma unroll
            for (int q = 0; q < 4; q++) acc[i][j][q] = 0.0f;

    /* ldmatrix lane addressing (byte offsets within a tile) */
    const int rowA = lane & 15, colA8 = (lane >= 16) ? 8 : 0;
    const int rowB = (lane & 7) + ((lane >= 16) ? 8 : 0);
    const int colB8 = (lane & 8) ? 8 : 0;
    /* A frag base for m-tile mt at k-halfstep ks:
       off = ((warp_m*32 + mt*16 + rowA)*SA + ks*16 + colA8)*2      */
    const uint32_t aoff = (uint32_t)((warp_m * 32 + rowA) * SA + colA8) * 2;
    /* B frag base for n-group g (16 cols) at ks:
       off = ((warp_n*32 + g*16 + rowB)*SA + ks*16 + colB8)*2       */
    const uint32_t boff = (uint32_t)((warp_n * 32 + rowB) * SA + colB8) * 2;

    float4 va0, va1, vb0, vb1;
    /* prologue: load + split chunk 0 into buf 0 */
    va0 = *(const float4*)(Ap);            va1 = *(const float4*)(Ap + 64 * KDIM);
    vb0 = *(const float4*)(Bp);            vb1 = *(const float4*)(Bp + 64 * KDIM);
    {
        uint2 hi, lo;
        uint32_t o0 = rL * SA + cL, o1 = (rL + 64) * SA + cL;
        split4(va0, hi, lo);
        *(uint2*)(s + 0 * TILE_HW + o0) = hi;  *(uint2*)(s + 1 * TILE_HW + o0) = lo;
        split4(va1, hi, lo);
        *(uint2*)(s + 0 * TILE_HW + o1) = hi;  *(uint2*)(s + 1 * TILE_HW + o1) = lo;
        split4(vb0, hi, lo);
        *(uint2*)(s + 2 * TILE_HW + o0) = hi;  *(uint2*)(s + 3 * TILE_HW + o0) = lo;
        split4(vb1, hi, lo);
        *(uint2*)(s + 2 * TILE_HW + o1) = hi;  *(uint2*)(s + 3 * TILE_HW + o1) = lo;
    }
    __syncthreads();

    for (int c = 0; c < NCHUNK; c++) {
        const int b = c & 1;
        /* issue gmem loads for chunk c+1 (latency covered by MMAs below) */
        if (c + 1 < NCHUNK) {
            int kc = (c + 1) * KC;
            va0 = *(const float4*)(Ap + kc); va1 = *(const float4*)(Ap + kc + 64 * KDIM);
            vb0 = *(const float4*)(Bp + kc); vb1 = *(const float4*)(Bp + kc + 64 * KDIM);
        }

        /* compute on buf b */
        const uint32_t tAh = sb + b * BUF_B + 0 * TILE_B;
        const uint32_t tAl = sb + b * BUF_B + 1 * TILE_B;
        const uint32_t tBh = sb + b * BUF_B + 2 * TILE_B;
        const uint32_t tBl = sb + b * BUF_B + 3 * TILE_B;
#pragma unroll
        for (int ks = 0; ks < 2; ks++) {
            const uint32_t ksoff = (uint32_t)(ks * 16) * 2;
            uint32_t ah[2][4], al[2][4], bh[2][4], bl[2][4];
#pragma unroll
            for (int mt = 0; mt < 2; mt++) {
                ldm_x4(ah[mt], tAh + aoff + ksoff + (uint32_t)(mt * 16 * SA) * 2);
                ldm_x4(al[mt], tAl + aoff + ksoff + (uint32_t)(mt * 16 * SA) * 2);
            }
#pragma unroll
            for (int g = 0; g < 2; g++) {
                ldm_x4(bh[g], tBh + boff + ksoff + (uint32_t)(g * 16 * SA) * 2);
                ldm_x4(bl[g], tBl + boff + ksoff + (uint32_t)(g * 16 * SA) * 2);
            }
#pragma unroll
            for (int mt = 0; mt < 2; mt++)
#pragma unroll
                for (int nt = 0; nt < 4; nt++) {
                    int g = nt >> 1, p = (nt & 1) * 2;
                    mma_bf16(acc[mt][nt], ah[mt], bh[g][p], bh[g][p + 1]);
                    mma_bf16(acc[mt][nt], ah[mt], bl[g][p], bl[g][p + 1]);
                    mma_bf16(acc[mt][nt], al[mt], bh[g][p], bh[g][p + 1]);
                }
        }

        /* split + store chunk c+1 into the other buffer */
        if (c + 1 < NCHUNK) {
            __nv_bfloat16* d = s + ((c + 1) & 1) * (BUF_B / 2);
            uint2 hi, lo;
            uint32_t o0 = rL * SA + cL, o1 = (rL + 64) * SA + cL;
            split4(va0, hi, lo);
            *(uint2*)(d + 0 * TILE_HW + o0) = hi; *(uint2*)(d + 1 * TILE_HW + o0) = lo;
            split4(va1, hi, lo);
            *(uint2*)(d + 0 * TILE_HW + o1) = hi; *(uint2*)(d + 1 * TILE_HW + o1) = lo;
            split4(vb0, hi, lo);
            *(uint2*)(d + 2 * TILE_HW + o0) = hi; *(uint2*)(d + 3 * TILE_HW + o0) = lo;
            split4(vb1, hi, lo);
            *(uint2*)(d + 2 * TILE_HW + o1) = hi; *(uint2*)(d + 3 * TILE_HW + o1) = lo;
        }
        __syncthreads();
    }

    /* epilogue: mma C fragment layout -> gmem */
    const int rowg = lane >> 2, colg = (lane & 3) * 2;
#pragma unroll
    for (int mt = 0; mt < 2; mt++) {
#pragma unroll
        for (int nt = 0; nt < 4; nt++) {
            int r = m0 + warp_m * 32 + mt * 16 + rowg;
            int cc = n0 + warp_n * 32 + nt * 8 + colg;
            *(float2*)(C + (size_t)r * KDIM + cc) =
                make_float2(acc[mt][nt][0], acc[mt][nt][1]);
            *(float2*)(C + (size_t)(r + 8) * KDIM + cc) =
                make_float2(acc[mt][nt][2], acc[mt][nt][3]);
        }
    }
}

/* ---------------- causal flash attention (fp32, online softmax) ---------- */
#define BM 64
#define BN 64
#define TSTRIDE 132
#define PSTRIDE 68

extern __shared__ float sh[];

__global__ void __launch_bounds__(256) flash_attn(const float* __restrict__ Q,
                                                  const float* __restrict__ Km,
                                                  const float* __restrict__ Vm,
                                                  float* __restrict__ O) {
    float* Qs = sh;
    float* Ks = Qs + BM * TSTRIDE;
    float* Vs = Ks + BN * TSTRIDE;
    float* Ps = Vs + BN * TSTRIDE;

    int qb = blockIdx.x, h = blockIdx.y, b = blockIdx.z;
    int tid = threadIdx.x, tx = tid & 15, ty = tid >> 4;
    int q0 = qb * BM;
    const float scale = 0.08838834764831845f;

    const float* Qbase = Q + (b * SQ) * HID + h * HD;
    for (int it = tid; it < BM * (HD / 4); it += 256) {
        int r = it >> 5, c4 = (it & 31) << 2;
        *(float4*)(Qs + r * TSTRIDE + c4) =
            *(const float4*)(Qbase + (q0 + r) * HID + c4);
    }

    float m_i[4], l_i[4], o[4][8];
#pragma unroll
    for (int i = 0; i < 4; i++) {
        m_i[i] = -1e30f; l_i[i] = 0.0f;
#pragma unroll
        for (int jj = 0; jj < 8; jj++) o[i][jj] = 0.0f;
    }

    for (int kb = 0; kb <= qb; kb++) {
        int k0 = kb * BN;
        const float* Kbase = Km + (b * SQ + k0) * HID + h * HD;
        const float* Vbase = Vm + (b * SQ + k0) * HID + h * HD;
        __syncthreads();
        for (int it = tid; it < BN * (HD / 4); it += 256) {
            int r = it >> 5, c4 = (it & 31) << 2;
            *(float4*)(Ks + r * TSTRIDE + c4) = *(const float4*)(Kbase + r * HID + c4);
            *(float4*)(Vs + r * TSTRIDE + c4) = *(const float4*)(Vbase + r * HID + c4);
        }
        __syncthreads();

        float s[4][4];
#pragma unroll
        for (int i = 0; i < 4; i++)
#pragma unroll
            for (int jj = 0; jj < 4; jj++) s[i][jj] = 0.0f;

#pragma unroll 4
        for (int d = 0; d < HD; d++) {
            float qr[4], kv[4];
#pragma unroll
            for (int i = 0; i < 4; i++) qr[i] = Qs[(ty * 4 + i) * TSTRIDE + d];
#pragma unroll
            for (int jj = 0; jj < 4; jj++) kv[jj] = Ks[(tx + 16 * jj) * TSTRIDE + d];
#pragma unroll
            for (int i = 0; i < 4; i++)
#pragma unroll
                for (int jj = 0; jj < 4; jj++)
                    s[i][jj] = fmaf(qr[i], kv[jj], s[i][jj]);
        }

#pragma unroll
        for (int i = 0; i < 4; i++) {
            int qi = q0 + ty * 4 + i;
#pragma unroll
            for (int jj = 0; jj < 4; jj++) {
                int ki = k0 + tx + 16 * jj;
                s[i][jj] = s[i][jj] * scale + (ki > qi ? -1e9f : 0.0f);
            }
        }

#pragma unroll
        for (int i = 0; i < 4; i++) {
            float mt = fmaxf(fmaxf(s[i][0], s[i][1]), fmaxf(s[i][2], s[i][3]));
#pragma unroll
            for (int off = 1; off < 16; off <<= 1)
                mt = fmaxf(mt, __shfl_xor_sync(0xffffffffu, mt, off));
            float mnew = fmaxf(m_i[i], mt);
            float alpha = __expf(m_i[i] - mnew);
            m_i[i] = mnew;
            float rowsum = 0.0f;
#pragma unroll
            for (int jj = 0; jj < 4; jj++) {
                float p = __expf(s[i][jj] - mnew);
                Ps[(ty * 4 + i) * PSTRIDE + tx + 16 * jj] = p;
                rowsum += p;
            }
#pragma unroll
            for (int off = 1; off < 16; off <<= 1)
                rowsum += __shfl_xor_sync(0xffffffffu, rowsum, off);
            l_i[i] = l_i[i] * alpha + rowsum;
#pragma unroll
            for (int jj = 0; jj < 8; jj++) o[i][jj] *= alpha;
        }
        __syncwarp();

#pragma unroll 2
        for (int kk = 0; kk < BN; kk++) {
            float pv[4], vv[8];
#pragma unroll
            for (int i = 0; i < 4; i++) pv[i] = Ps[(ty * 4 + i) * PSTRIDE + kk];
#pragma unroll
            for (int jj = 0; jj < 8; jj++) vv[jj] = Vs[kk * TSTRIDE + tx + 16 * jj];
#pragma unroll
            for (int i = 0; i < 4; i++)
#pragma unroll
                for (int jj = 0; jj < 8; jj++)
                    o[i][jj] = fmaf(pv[i], vv[jj], o[i][jj]);
        }
    }

#pragma unroll
    for (int i = 0; i < 4; i++) {
        float inv = 1.0f / l_i[i];
        float* Orow = O + (b * SQ + q0 + ty * 4 + i) * HID + h * HD + tx;
#pragma unroll
        for (int jj = 0; jj < 8; jj++) Orow[16 * jj] = o[i][jj] * inv;
    }
}

/* ---------------- launcher ---------------------------------------------- */
extern "C" void kernel_launch(void* const* d_in, const int* in_sizes, int n_in,
                              void* d_out, int out_size) {
    (void)n_in; (void)out_size;
    const float* x   = (const float*)d_in[0];
    const float* cpq = (const float*)d_in[1];
    const float* cpk = (const float*)d_in[2];
    const float* cpv = (const float*)d_in[3];
    const float* cpo = (const float*)d_in[4];
    float* out = (float*)d_out;
    int ncp = in_sizes[1];

    float *pW, *pQ, *pK, *pV, *pA;
    cudaGetSymbolAddress((void**)&pW, g_W);
    cudaGetSymbolAddress((void**)&pQ, g_Q);
    cudaGetSymbolAddress((void**)&pK, g_K);
    cudaGetSymbolAddress((void**)&pV, g_V);
    cudaGetSymbolAddress((void**)&pA, g_A);

    build_weights<<<(NW + 255) / 256, 256>>>(cpq, cpk, cpv, cpo, ncp);

    cudaFuncSetAttribute(gemm_hmma, cudaFuncAttributeMaxDynamicSharedMemorySize,
                         GEMM_SMEM);
    dim3 gg(HID / 128, MROWS / 128);
    gemm_hmma<<<gg, 512, GEMM_SMEM>>>(x, pW + 0 * (size_t)NW, pQ);
    gemm_hmma<<<gg, 512, GEMM_SMEM>>>(x, pW + 1 * (size_t)NW, pK);
    gemm_hmma<<<gg, 512, GEMM_SMEM>>>(x, pW + 2 * (size_t)NW, pV);

    size_t shb = (size_t)(3 * BM * TSTRIDE + BM * PSTRIDE) * sizeof(float);
    cudaFuncSetAttribute(flash_attn, cudaFuncAttributeMaxDynamicSharedMemorySize,
                         (int)shb);
    flash_attn<<<dim3(SQ / BM, NHEAD, NB), 256, shb>>>(pQ, pK, pV, pA);

    gemm_hmma<<<gg, 512, GEMM_SMEM>>>(pA, pW + 3 * (size_t)NW, out);
}

// round 5
// speedup vs baseline: 2.9000x; 1.5136x over previous
#include <cuda_runtime.h>
#include <cuda_bf16.h>
#include <math.h>
#include <stdint.h>

#define HID   2048
#define NB    2
#define SQ    2048
#define NHEAD 16
#define HD    128
#define MROWS (NB * SQ)        /* 4096 */
#define NW    (HID * HID)      /* 4194304 */
#define KDIM  2048

/* ---------------- scratch (device globals; no allocation allowed) -------- */
__device__ float g_W[4][NW];
__device__ float g_Q[MROWS * HID];
__device__ float g_K[MROWS * HID];
__device__ float g_V[MROWS * HID];
__device__ float g_A[MROWS * HID];

__device__ __forceinline__ uint32_t smem_u32(const void* p) {
    uint32_t a;
    asm("{ .reg .u64 t; cvta.to.shared.u64 t, %1; cvt.u32.u64 %0, t; }"
        : "=r"(a) : "l"(p));
    return a;
}
__device__ __forceinline__ void ldm_x4(uint32_t* r, uint32_t addr) {
    asm volatile("ldmatrix.sync.aligned.m8n8.x4.shared.b16 {%0,%1,%2,%3}, [%4];"
                 : "=r"(r[0]), "=r"(r[1]), "=r"(r[2]), "=r"(r[3]) : "r"(addr));
}
__device__ __forceinline__ void mma_bf16(float* d, const uint32_t* a,
                                         uint32_t b0, uint32_t b1) {
    asm volatile("mma.sync.aligned.m16n8k16.row.col.f32.bf16.bf16.f32 "
                 "{%0,%1,%2,%3},{%4,%5,%6,%7},{%8,%9},{%0,%1,%2,%3};"
                 : "+f"(d[0]), "+f"(d[1]), "+f"(d[2]), "+f"(d[3])
                 : "r"(a[0]), "r"(a[1]), "r"(a[2]), "r"(a[3]), "r"(b0), "r"(b1));
}
__device__ __forceinline__ void split4(float4 v, uint2& hi, uint2& lo) {
    __nv_bfloat162 h0 = __float22bfloat162_rn(make_float2(v.x, v.y));
    __nv_bfloat162 h1 = __float22bfloat162_rn(make_float2(v.z, v.w));
    float2 f0 = __bfloat1622float2(h0), f1 = __bfloat1622float2(h1);
    __nv_bfloat162 l0 = __float22bfloat162_rn(make_float2(v.x - f0.x, v.y - f0.y));
    __nv_bfloat162 l1 = __float22bfloat162_rn(make_float2(v.z - f1.x, v.w - f1.y));
    hi = make_uint2(*(uint32_t*)&h0, *(uint32_t*)&h1);
    lo = make_uint2(*(uint32_t*)&l0, *(uint32_t*)&l1);
}
__device__ __forceinline__ uint32_t pack_hi(float a, float b) {
    __nv_bfloat162 h = __float22bfloat162_rn(make_float2(a, b));
    return *(uint32_t*)&h;
}
__device__ __forceinline__ uint32_t pack_lo(float a, float b, uint32_t hi) {
    float2 f = __bfloat1622float2(*(__nv_bfloat162*)&hi);
    __nv_bfloat162 l = __float22bfloat162_rn(make_float2(a - f.x, b - f.y));
    return *(uint32_t*)&l;
}

/* ---------------- weight reconstruction (fp32-matched jnp.interp) -------- */
__global__ void build_weights(const float* __restrict__ cpq,
                              const float* __restrict__ cpk,
                              const float* __restrict__ cpv,
                              const float* __restrict__ cpo,
                              int ncp) {
    int i = blockIdx.x * 256 + threadIdx.x;
    if (i >= NW) return;
    const float dT = 1.0f / (float)(NW - 1);
    const float dX = 1.0f / (float)(ncp - 1);
    float t = (float)i * dT;
    int j = (int)((double)t * (double)(ncp - 1));
    if (j > ncp - 2) j = ncp - 2;
    if (j < 0) j = 0;
    while (j < ncp - 2 && (float)(j + 1) * dX <= t) j++;
    while (j > 0 && (float)j * dX > t) j--;
    float x0 = (float)j * dX;
    float x1 = (float)(j + 1) * dX;
    float f  = (t - x0) / (x1 - x0);
    float aq = cpq[j], ak = cpk[j], av = cpv[j], ao = cpo[j];
    g_W[0][i] = fmaf(cpq[j + 1] - aq, f, aq);
    g_W[1][i] = fmaf(cpk[j + 1] - ak, f, ak);
    g_W[2][i] = fmaf(cpv[j + 1] - av, f, av);
    g_W[3][i] = fmaf(cpo[j + 1] - ao, f, ao);
}

/* =============== bf16x3 split HMMA GEMM: C[M,2048] = A * B^T ============= */
#define KC     32
#define NCHUNK (KDIM / KC)
#define SA     40
#define TILE_HW (128 * SA)
#define TILE_B  (TILE_HW * 2)
#define BUF_B   (4 * TILE_B)
#define GEMM_SMEM (2 * BUF_B)

__global__ void __launch_bounds__(512) gemm_hmma(const float* __restrict__ A,
                                                 const float* __restrict__ B,
                                                 float* __restrict__ C) {
    extern __shared__ char shg[];
    __nv_bfloat16* s = (__nv_bfloat16*)shg;
    const uint32_t sb = smem_u32(shg);
    const int tid = threadIdx.x;
    const int lane = tid & 31, wid = tid >> 5;
    const int warp_m = wid >> 2, warp_n = wid & 3;
    const int m0 = blockIdx.y * 128, n0 = blockIdx.x * 128;

    const int rL = tid >> 3, cL = (tid & 7) << 2;
    const float* Ap = A + (size_t)(m0 + rL) * KDIM + cL;
    const float* Bp = B + (size_t)(n0 + rL) * KDIM + cL;

    float acc[2][4][4];
#pragma unroll
    for (int i = 0; i < 2; i++)
#pragma unroll
        for (int j = 0; j < 4; j++)
#pragma unroll
            for (int q = 0; q < 4; q++) acc[i][j][q] = 0.0f;

    const int rowA = lane & 15, colA8 = (lane >= 16) ? 8 : 0;
    const int rowB = (lane & 7) + ((lane >= 16) ? 8 : 0);
    const int colB8 = (lane & 8) ? 8 : 0;
    const uint32_t aoff = (uint32_t)((warp_m * 32 + rowA) * SA + colA8) * 2;
    const uint32_t boff = (uint32_t)((warp_n * 32 + rowB) * SA + colB8) * 2;

    float4 va0, va1, vb0, vb1;
    va0 = *(const float4*)(Ap);            va1 = *(const float4*)(Ap + 64 * KDIM);
    vb0 = *(const float4*)(Bp);            vb1 = *(const float4*)(Bp + 64 * KDIM);
    {
        uint2 hi, lo;
        uint32_t o0 = rL * SA + cL, o1 = (rL + 64) * SA + cL;
        split4(va0, hi, lo);
        *(uint2*)(s + 0 * TILE_HW + o0) = hi;  *(uint2*)(s + 1 * TILE_HW + o0) = lo;
        split4(va1, hi, lo);
        *(uint2*)(s + 0 * TILE_HW + o1) = hi;  *(uint2*)(s + 1 * TILE_HW + o1) = lo;
        split4(vb0, hi, lo);
        *(uint2*)(s + 2 * TILE_HW + o0) = hi;  *(uint2*)(s + 3 * TILE_HW + o0) = lo;
        split4(vb1, hi, lo);
        *(uint2*)(s + 2 * TILE_HW + o1) = hi;  *(uint2*)(s + 3 * TILE_HW + o1) = lo;
    }
    __syncthreads();

    for (int c = 0; c < NCHUNK; c++) {
        const int b = c & 1;
        if (c + 1 < NCHUNK) {
            int kc = (c + 1) * KC;
            va0 = *(const float4*)(Ap + kc); va1 = *(const float4*)(Ap + kc + 64 * KDIM);
            vb0 = *(const float4*)(Bp + kc); vb1 = *(const float4*)(Bp + kc + 64 * KDIM);
        }

        const uint32_t tAh = sb + b * BUF_B + 0 * TILE_B;
        const uint32_t tAl = sb + b * BUF_B + 1 * TILE_B;
        const uint32_t tBh = sb + b * BUF_B + 2 * TILE_B;
        const uint32_t tBl = sb + b * BUF_B + 3 * TILE_B;
#pragma unroll
        for (int ks = 0; ks < 2; ks++) {
            const uint32_t ksoff = (uint32_t)(ks * 16) * 2;
            uint32_t ah[2][4], al[2][4], bh[2][4], bl[2][4];
#pragma unroll
            for (int mt = 0; mt < 2; mt++) {
                ldm_x4(ah[mt], tAh + aoff + ksoff + (uint32_t)(mt * 16 * SA) * 2);
                ldm_x4(al[mt], tAl + aoff + ksoff + (uint32_t)(mt * 16 * SA) * 2);
            }
#pragma unroll
            for (int g = 0; g < 2; g++) {
                ldm_x4(bh[g], tBh + boff + ksoff + (uint32_t)(g * 16 * SA) * 2);
                ldm_x4(bl[g], tBl + boff + ksoff + (uint32_t)(g * 16 * SA) * 2);
            }
#pragma unroll
            for (int mt = 0; mt < 2; mt++)
#pragma unroll
                for (int nt = 0; nt < 4; nt++) {
                    int g = nt >> 1, p = (nt & 1) * 2;
                    mma_bf16(acc[mt][nt], ah[mt], bh[g][p], bh[g][p + 1]);
                    mma_bf16(acc[mt][nt], ah[mt], bl[g][p], bl[g][p + 1]);
                    mma_bf16(acc[mt][nt], al[mt], bh[g][p], bh[g][p + 1]);
                }
        }

        if (c + 1 < NCHUNK) {
            __nv_bfloat16* d = s + ((c + 1) & 1) * (BUF_B / 2);
            uint2 hi, lo;
            uint32_t o0 = rL * SA + cL, o1 = (rL + 64) * SA + cL;
            split4(va0, hi, lo);
            *(uint2*)(d + 0 * TILE_HW + o0) = hi; *(uint2*)(d + 1 * TILE_HW + o0) = lo;
            split4(va1, hi, lo);
            *(uint2*)(d + 0 * TILE_HW + o1) = hi; *(uint2*)(d + 1 * TILE_HW + o1) = lo;
            split4(vb0, hi, lo);
            *(uint2*)(d + 2 * TILE_HW + o0) = hi; *(uint2*)(d + 3 * TILE_HW + o0) = lo;
            split4(vb1, hi, lo);
            *(uint2*)(d + 2 * TILE_HW + o1) = hi; *(uint2*)(d + 3 * TILE_HW + o1) = lo;
        }
        __syncthreads();
    }

    const int rowg = lane >> 2, colg = (lane & 3) * 2;
#pragma unroll
    for (int mt = 0; mt < 2; mt++) {
#pragma unroll
        for (int nt = 0; nt < 4; nt++) {
            int r = m0 + warp_m * 32 + mt * 16 + rowg;
            int cc = n0 + warp_n * 32 + nt * 8 + colg;
            *(float2*)(C + (size_t)r * KDIM + cc) =
                make_float2(acc[mt][nt][0], acc[mt][nt][1]);
            *(float2*)(C + (size_t)(r + 8) * KDIM + cc) =
                make_float2(acc[mt][nt][2], acc[mt][nt][3]);
        }
    }
}

/* ========== bf16x3 HMMA causal flash attention =========================== */
/* CTA: 128 q-rows x 64-key blocks, 8 warps (16 rows each), 256 threads.    */
#define FKS 136                 /* Q/K smem halfword stride (272 B)         */
#define FVS 72                  /* VT smem halfword stride (144 B)          */
#define OFF_QH 0
#define OFF_QL (128 * FKS)
#define OFF_KH (2 * 128 * FKS)
#define OFF_KL (OFF_KH + 64 * FKS)
#define OFF_VH (OFF_KL + 64 * FKS)
#define OFF_VL (OFF_VH + 128 * FVS)
#define FL_SMEM ((OFF_VL + 128 * FVS) * 2)

__global__ void __launch_bounds__(256, 1) flash_hmma(const float* __restrict__ Q,
                                                     const float* __restrict__ Km,
                                                     const float* __restrict__ Vm,
                                                     float* __restrict__ O) {
    extern __shared__ char shf[];
    __nv_bfloat16* s = (__nv_bfloat16*)shf;
    const uint32_t sb = smem_u32(shf);
    const int tid = threadIdx.x, lane = tid & 31, wid = tid >> 5;
    const int qb = blockIdx.x, h = blockIdx.y, b = blockIdx.z;
    const int q0 = qb * 128;
    const int wm0 = wid * 16;                 /* warp row base within tile */
    const float scale = 0.08838834764831845f; /* 1/sqrt(128) */

    /* ---- load Q tile (hi/lo split) ---- */
    const float* Qg = Q + (size_t)(b * SQ + q0) * HID + h * HD;
#pragma unroll
    for (int it = 0; it < 16; it++) {
        int idx = tid + it * 256;
        int r = idx >> 5, c4 = (idx & 31) << 2;
        float4 v = *(const float4*)(Qg + (size_t)r * HID + c4);
        uint2 hi, lo; split4(v, hi, lo);
        *(uint2*)(s + OFF_QH + r * FKS + c4) = hi;
        *(uint2*)(s + OFF_QL + r * FKS + c4) = lo;
    }

    /* ---- per-lane ldmatrix base addresses ---- */
    const uint32_t aBaseH = sb + 2u * (OFF_QH + (wm0 + (lane & 15)) * FKS + ((lane >> 4) << 3));
    const uint32_t aBaseL = sb + 2u * (OFF_QL + (wm0 + (lane & 15)) * FKS + ((lane >> 4) << 3));
    const int krow = (lane & 7) + ((lane >> 4) << 3);
    const uint32_t kBaseH = sb + 2u * (OFF_KH + krow * FKS + (lane & 8));
    const uint32_t kBaseL = sb + 2u * (OFF_KL + krow * FKS + (lane & 8));
    const uint32_t vBaseH = sb + 2u * (OFF_VH + krow * FVS + (lane & 8));
    const uint32_t vBaseL = sb + 2u * (OFF_VL + krow * FVS + (lane & 8));

    float acc_o[16][4];
#pragma unroll
    for (int i = 0; i < 16; i++)
#pragma unroll
        for (int j = 0; j < 4; j++) acc_o[i][j] = 0.0f;
    float m0r = -1e30f, m1r = -1e30f, l0r = 0.0f, l1r = 0.0f;

    const int kb_max = 2 * qb + 1;
    const int r0g = q0 + wm0 + (lane >> 2);   /* global row of c0/c1 */
    const int r1g = r0g + 8;

    for (int kb = 0; kb <= kb_max; kb++) {
        const int k0 = kb * 64;
        __syncthreads();
        /* ---- load K block [key][d] ---- */
        const float* Kg = Km + (size_t)(b * SQ + k0) * HID + h * HD;
#pragma unroll
        for (int it = 0; it < 8; it++) {
            int idx = tid + it * 256;
            int r = idx >> 5, c4 = (idx & 31) << 2;
            float4 v = *(const float4*)(Kg + (size_t)r * HID + c4);
            uint2 hi, lo; split4(v, hi, lo);
            *(uint2*)(s + OFF_KH + r * FKS + c4) = hi;
            *(uint2*)(s + OFF_KL + r * FKS + c4) = lo;
        }
        /* ---- load V block transposed -> VT[d][key] ---- */
        const float* Vg = Vm + (size_t)(b * SQ + k0) * HID + h * HD;
#pragma unroll
        for (int it = 0; it < 8; it++) {
            int idx = tid + it * 256;
            int r = idx & 63, c4 = (idx >> 6) << 2;
            float4 v = *(const float4*)(Vg + (size_t)r * HID + c4);
            float e[4] = {v.x, v.y, v.z, v.w};
#pragma unroll
            for (int q = 0; q < 4; q++) {
                __nv_bfloat16 hb = __float2bfloat16_rn(e[q]);
                __nv_bfloat16 lb = __float2bfloat16_rn(e[q] - __bfloat162float(hb));
                s[OFF_VH + (c4 + q) * FVS + r] = hb;
                s[OFF_VL + (c4 + q) * FVS + r] = lb;
            }
        }
        __syncthreads();

        if (k0 > q0 + wm0) continue;          /* warp fully above diagonal */

        /* ---- S = Q K^T (bf16x3) ---- */
        float accs[8][4];
#pragma unroll
        for (int i = 0; i < 8; i++)
#pragma unroll
            for (int j = 0; j < 4; j++) accs[i][j] = 0.0f;
#pragma unroll
        for (int ks = 0; ks < 8; ks++) {
            uint32_t ah[4], al[4];
            ldm_x4(ah, aBaseH + ks * 32);
            ldm_x4(al, aBaseL + ks * 32);
#pragma unroll
            for (int ng = 0; ng < 4; ng++) {
                uint32_t bh[4], bl[4];
                ldm_x4(bh, kBaseH + (uint32_t)(ng * 16 * FKS) * 2 + ks * 32);
                ldm_x4(bl, kBaseL + (uint32_t)(ng * 16 * FKS) * 2 + ks * 32);
                mma_bf16(accs[2 * ng],     ah, bh[0], bh[1]);
                mma_bf16(accs[2 * ng],     ah, bl[0], bl[1]);
                mma_bf16(accs[2 * ng],     al, bh[0], bh[1]);
                mma_bf16(accs[2 * ng + 1], ah, bh[2], bh[3]);
                mma_bf16(accs[2 * ng + 1], ah, bl[2], bl[3]);
                mma_bf16(accs[2 * ng + 1], al, bh[2], bh[3]);
            }
        }

        /* ---- scale + causal mask ---- */
#pragma unroll
        for (int nt = 0; nt < 8; nt++) {
            int cb = k0 + nt * 8 + (lane & 3) * 2;
            accs[nt][0] = accs[nt][0] * scale + ((cb     > r0g) ? -1e9f : 0.0f);
            accs[nt][1] = accs[nt][1] * scale + ((cb + 1 > r0g) ? -1e9f : 0.0f);
            accs[nt][2] = accs[nt][2] * scale + ((cb     > r1g) ? -1e9f : 0.0f);
            accs[nt][3] = accs[nt][3] * scale + ((cb + 1 > r1g) ? -1e9f : 0.0f);
        }

        /* ---- online softmax (warp-local rows) ---- */
        float mx0 = -1e30f, mx1 = -1e30f;
#pragma unroll
        for (int nt = 0; nt < 8; nt++) {
            mx0 = fmaxf(mx0, fmaxf(accs[nt][0], accs[nt][1]));
            mx1 = fmaxf(mx1, fmaxf(accs[nt][2], accs[nt][3]));
        }
        mx0 = fmaxf(mx0, __shfl_xor_sync(0xffffffffu, mx0, 1));
        mx0 = fmaxf(mx0, __shfl_xor_sync(0xffffffffu, mx0, 2));
        mx1 = fmaxf(mx1, __shfl_xor_sync(0xffffffffu, mx1, 1));
        mx1 = fmaxf(mx1, __shfl_xor_sync(0xffffffffu, mx1, 2));
        float mn0 = fmaxf(m0r, mx0), mn1 = fmaxf(m1r, mx1);
        float al0 = __expf(m0r - mn0), al1 = __expf(m1r - mn1);
        m0r = mn0; m1r = mn1;
        float rs0 = 0.0f, rs1 = 0.0f;
#pragma unroll
        for (int nt = 0; nt < 8; nt++) {
            accs[nt][0] = __expf(accs[nt][0] - mn0);
            accs[nt][1] = __expf(accs[nt][1] - mn0);
            accs[nt][2] = __expf(accs[nt][2] - mn1);
            accs[nt][3] = __expf(accs[nt][3] - mn1);
            rs0 += accs[nt][0] + accs[nt][1];
            rs1 += accs[nt][2] + accs[nt][3];
        }
        rs0 += __shfl_xor_sync(0xffffffffu, rs0, 1);
        rs0 += __shfl_xor_sync(0xffffffffu, rs0, 2);
        rs1 += __shfl_xor_sync(0xffffffffu, rs1, 1);
        rs1 += __shfl_xor_sync(0xffffffffu, rs1, 2);
        l0r = l0r * al0 + rs0;
        l1r = l1r * al1 + rs1;
#pragma unroll
        for (int i = 0; i < 16; i++) {
            acc_o[i][0] *= al0; acc_o[i][1] *= al0;
            acc_o[i][2] *= al1; acc_o[i][3] *= al1;
        }

        /* ---- P fragments (A-operand) straight from S accumulators ---- */
        uint32_t ph[4][4], pl[4][4];
#pragma unroll
        for (int kk = 0; kk < 4; kk++) {
            int n0t = 2 * kk, n1t = 2 * kk + 1;
            ph[kk][0] = pack_hi(accs[n0t][0], accs[n0t][1]);
            pl[kk][0] = pack_lo(accs[n0t][0], accs[n0t][1], ph[kk][0]);
            ph[kk][1] = pack_hi(accs[n0t][2], accs[n0t][3]);
            pl[kk][1] = pack_lo(accs[n0t][2], accs[n0t][3], ph[kk][1]);
            ph[kk][2] = pack_hi(accs[n1t][0], accs[n1t][1]);
            pl[kk][2] = pack_lo(accs[n1t][0], accs[n1t][1], ph[kk][2]);
            ph[kk][3] = pack_hi(accs[n1t][2], accs[n1t][3]);
            pl[kk][3] = pack_lo(accs[n1t][2], accs[n1t][3], ph[kk][3]);
        }

        /* ---- O += P V (bf16x3) ---- */
#pragma unroll
        for (int kk = 0; kk < 4; kk++) {
#pragma unroll
            for (int g = 0; g < 8; g++) {
                uint32_t vh[4], vl[4];
                ldm_x4(vh, vBaseH + (uint32_t)(g * 16 * FVS) * 2 + kk * 32);
                ldm_x4(vl, vBaseL + (uint32_t)(g * 16 * FVS) * 2 + kk * 32);
                mma_bf16(acc_o[2 * g],     ph[kk], vh[0], vh[1]);
                mma_bf16(acc_o[2 * g],     ph[kk], vl[0], vl[1]);
                mma_bf16(acc_o[2 * g],     pl[kk], vh[0], vh[1]);
                mma_bf16(acc_o[2 * g + 1], ph[kk], vh[2], vh[3]);
                mma_bf16(acc_o[2 * g + 1], ph[kk], vl[2], vl[3]);
                mma_bf16(acc_o[2 * g + 1], pl[kk], vh[2], vh[3]);
            }
        }
    }

    /* ---- epilogue ---- */
    float inv0 = 1.0f / l0r, inv1 = 1.0f / l1r;
    float* Og = O + (size_t)(b * SQ + r0g) * HID + h * HD;
#pragma unroll
    for (int nto = 0; nto < 16; nto++) {
        int c = nto * 8 + (lane & 3) * 2;
        *(float2*)(Og + c) = make_float2(acc_o[nto][0] * inv0, acc_o[nto][1] * inv0);
        *(float2*)(Og + (size_t)8 * HID + c) =
            make_float2(acc_o[nto][2] * inv1, acc_o[nto][3] * inv1);
    }
}

/* ---------------- launcher ---------------------------------------------- */
extern "C" void kernel_launch(void* const* d_in, const int* in_sizes, int n_in,
                              void* d_out, int out_size) {
    (void)n_in; (void)out_size;
    const float* x   = (const float*)d_in[0];
    const float* cpq = (const float*)d_in[1];
    const float* cpk = (const float*)d_in[2];
    const float* cpv = (const float*)d_in[3];
    const float* cpo = (const float*)d_in[4];
    float* out = (float*)d_out;
    int ncp = in_sizes[1];

    float *pW, *pQ, *pK, *pV, *pA;
    cudaGetSymbolAddress((void**)&pW, g_W);
    cudaGetSymbolAddress((void**)&pQ, g_Q);
    cudaGetSymbolAddress((void**)&pK, g_K);
    cudaGetSymbolAddress((void**)&pV, g_V);
    cudaGetSymbolAddress((void**)&pA, g_A);

    build_weights<<<(NW + 255) / 256, 256>>>(cpq, cpk, cpv, cpo, ncp);

    cudaFuncSetAttribute(gemm_hmma, cudaFuncAttributeMaxDynamicSharedMemorySize,
                         GEMM_SMEM);
    dim3 gg(HID / 128, MROWS / 128);
    gemm_hmma<<<gg, 512, GEMM_SMEM>>>(x, pW + 0 * (size_t)NW, pQ);
    gemm_hmma<<<gg, 512, GEMM_SMEM>>>(x, pW + 1 * (size_t)NW, pK);
    gemm_hmma<<<gg, 512, GEMM_SMEM>>>(x, pW + 2 * (size_t)NW, pV);

    cudaFuncSetAttribute(flash_hmma, cudaFuncAttributeMaxDynamicSharedMemorySize,
                         FL_SMEM);
    flash_hmma<<<dim3(SQ / 128, NHEAD, NB), 256, FL_SMEM>>>(pQ, pK, pV, pA);

    gemm_hmma<<<gg, 512, GEMM_SMEM>>>(pA, pW + 3 * (size_t)NW, out);
}